// round 10
// baseline (speedup 1.0000x reference)
#include <cuda_runtime.h>
#include <cuda_bf16.h>
#include <cstdint>

#define B_   128
#define T_   512
#define D_   256
#define H_   512
#define G_   2048
#define K0_  768
#define K1_  1024
#define NKT0 (K0_ / 16)      // 48 ktiles
#define NKT1 (K1_ / 16)      // 64 ktiles
#define NCTA 128
#define NTHR 512
#define BH   (B_ * H_)

// ---------------- persistent device scratch -----------------------------------
// Weight fragments, B-frag lane order: [ntg(256)][kt][s=hi/lo][lane(32)][4 bf16]
__device__ uint4 g_Wf0[(size_t)256 * NKT0 * 2 * 16];   // 6 MB
__device__ uint4 g_Wf1[(size_t)256 * NKT1 * 2 * 16];   // 8 MB
__device__ float g_b0[G_];
__device__ float g_b1[G_];
__device__ uint32_t g_xp[(size_t)T_ * B_ * D_];        // packed hi|lo<<16, [t][b][d]
__device__ uint32_t g_hp[2][2][BH];                    // [layer][buf][b*H + col]
__device__ unsigned g_count;
__device__ unsigned g_release;

// ---------------- helpers -------------------------------------------------------
__device__ __forceinline__ float sigm(float v) { return 1.f / (1.f + __expf(-v)); }

__device__ __forceinline__ uint32_t pack_split(float v) {
    __nv_bfloat16 h = __float2bfloat16(v);
    __nv_bfloat16 l = __float2bfloat16(v - __bfloat162float(h));
    return (uint32_t)__bfloat16_as_ushort(h) |
           ((uint32_t)__bfloat16_as_ushort(l) << 16);
}

__device__ __forceinline__ uint32_t prmt(uint32_t a, uint32_t b, uint32_t c) {
    uint32_t r;
    asm("prmt.b32 %0, %1, %2, %3;" : "=r"(r) : "r"(a), "r"(b), "r"(c));
    return r;
}

__device__ __forceinline__ void mma16816(float* d, const uint32_t* a, uint2 b) {
    asm volatile(
        "mma.sync.aligned.m16n8k16.row.col.f32.bf16.bf16.f32 "
        "{%0,%1,%2,%3}, {%4,%5,%6,%7}, {%8,%9}, {%0,%1,%2,%3};"
        : "+f"(d[0]), "+f"(d[1]), "+f"(d[2]), "+f"(d[3])
        : "r"(a[0]), "r"(a[1]), "r"(a[2]), "r"(a[3]), "r"(b.x), "r"(b.y));
}

__device__ __forceinline__ void gridBarrier(unsigned target) {
    __syncthreads();
    if (threadIdx.x == 0) {
        __threadfence();
        unsigned t = atomicAdd(&g_count, 1u);
        if (t == (unsigned)(NCTA - 1)) {
            g_count = 0;
            __threadfence();
            atomicAdd(&g_release, 1u);
        } else {
            while ((int)(*(volatile unsigned*)&g_release - target) < 0) {}
        }
        __threadfence();
    }
    __syncthreads();
}

// bf16-split store of W[np][k] into fragment layout (hi plane + lo plane)
__device__ __forceinline__ void wf_store(__nv_bfloat16* base, int NKT,
                                         int np, int k, float v) {
    __nv_bfloat16 h = __float2bfloat16(v);
    __nv_bfloat16 l = __float2bfloat16(v - __bfloat162float(h));
    int ntg = np >> 3;
    int ln = ((np & 7) << 2) | ((k >> 1) & 3);   // B-frag: n = lane/4, k-pair = lane%4
    int kt = k >> 4, b = (k >> 3) & 1, e = k & 1;
    size_t o = ((((size_t)ntg * NKT + kt) * 2) * 32 + ln) * 4 + b * 2 + e;
    base[o] = h;
    base[o + 128] = l;   // s=1 plane is +32*4 elements
}

// ---------------- prep kernels ---------------------------------------------------
__global__ void prep_x(const float* __restrict__ x) {
    const size_t total = (size_t)T_ * B_ * D_;
    for (size_t i = (size_t)blockIdx.x * blockDim.x + threadIdx.x; i < total;
         i += (size_t)gridDim.x * blockDim.x) {
        int t = (int)(i / (B_ * D_));
        int r = (int)(i % (B_ * D_));
        int b = r / D_, d = r % D_;
        g_xp[i] = pack_split(x[(size_t)b * T_ * D_ + (size_t)t * D_ + d]);
    }
}

// W0[np][k<256] = folded proj; b0
__global__ void prep_w0(const float* __restrict__ wx0, const float* __restrict__ projw,
                        const float* __restrict__ projb, const float* __restrict__ bx0,
                        const float* __restrict__ bh0) {
    int np = blockIdx.x;
    int jcol = np >> 2, q = np & 3;
    int n = q * H_ + jcol;
    int d = threadIdx.x;
    const float* wrow = wx0 + (size_t)n * D_;
    float acc = 0.f;
    for (int j = 0; j < D_; ++j) acc += wrow[j] * projw[(size_t)j * D_ + d];
    wf_store((__nv_bfloat16*)g_Wf0, NKT0, np, d, acc);
    if (d == 0) {
        float bb = bx0[n] + bh0[n];
        for (int j = 0; j < D_; ++j) bb += wrow[j] * projb[j];
        g_b0[np] = bb;
    }
}

// W0[np][k>=256] = wh0 ; W1 = [wx1|wh1] ; b1
__global__ void prep_rest(const float* __restrict__ wh0, const float* __restrict__ wx1,
                          const float* __restrict__ wh1, const float* __restrict__ bx1,
                          const float* __restrict__ bh1) {
    const int total = G_ * H_ + G_ * K1_ + G_;
    for (int i = blockIdx.x * blockDim.x + threadIdx.x; i < total;
         i += gridDim.x * blockDim.x) {
        if (i < G_ * H_) {
            int np = i / H_, k = i % H_;
            int n = (np & 3) * H_ + (np >> 2);
            wf_store((__nv_bfloat16*)g_Wf0, NKT0, np, D_ + k,
                     wh0[(size_t)n * H_ + k]);
        } else if (i < G_ * H_ + G_ * K1_) {
            int r = i - G_ * H_;
            int np = r / K1_, k = r % K1_;
            int n = (np & 3) * H_ + (np >> 2);
            float v = (k < H_) ? wx1[(size_t)n * H_ + k]
                               : wh1[(size_t)n * H_ + (k - H_)];
            wf_store((__nv_bfloat16*)g_Wf1, NKT1, np, k, v);
        } else {
            int np = i - G_ * H_ - G_ * K1_;
            int n = (np & 3) * H_ + (np >> 2);
            g_b1[np] = bx1[n] + bh1[n];
        }
    }
}

// ---------------- A fragment loads (packed u32, direct from global) -------------
// M=16 per warp: rows r0, r0+8; k pairs kq, kq+8.
__device__ __forceinline__ void ldA(uint2* a, int kt,
    const uint32_t* __restrict__ s1, int st1,
    const uint32_t* __restrict__ s2, int len1, int r0, int kq) {
    int kb = kt << 4;
    const uint32_t* s;
    int st;
    if (kb < len1) { s = s1 + kb + kq; st = st1; }
    else           { s = s2 + (kb - len1) + kq; st = H_; }
    const uint32_t* p0 = s + (size_t)r0 * st;
#pragma unroll
    for (int rp = 0; rp < 2; ++rp) {
        const uint32_t* p = p0 + (size_t)(rp * 8) * st;
        a[rp]     = *(const uint2*)p;        // a0/a1: k pair
        a[rp + 2] = *(const uint2*)(p + 8);  // a2/a3: k pair + 8
    }
}

// ---------------- one LSTM phase: bf16-split mma + cell epilogue -----------------
// 16 warps = 8 M-groups x 2 N-groups; each warp M=16 rows x N=16 gate-cols.
template <int NKT>
__device__ void lstm_phase(const uint32_t* __restrict__ sW,
    const uint32_t* __restrict__ src1, int st1,
    const uint32_t* __restrict__ src2, int len1,
    uint32_t* __restrict__ hOut, float* cst,
    const float* __restrict__ sbias, uint32_t* __restrict__ bounce, int jcol0) {
    const int tid = threadIdx.x;
    const int lane = tid & 31, w = tid >> 5;
    const int mg = w >> 1, ng = w & 1;
    const int r0 = mg * 16 + (lane >> 2);
    const int kq = (lane & 3) << 1;

    float acc[2][4];
#pragma unroll
    for (int j = 0; j < 2; ++j)
#pragma unroll
        for (int k = 0; k < 4; ++k) acc[j][k] = 0.f;

    uint2 ab[4][4];
#pragma unroll
    for (int p = 0; p < 4; ++p)
        ldA(ab[p], p, src1, st1, src2, len1, r0, kq);

#pragma unroll 4
    for (int kt = 0; kt < NKT; ++kt) {
        uint2* cur = ab[kt & 3];
        uint32_t ah[4], al[4];
#pragma unroll
        for (int j = 0; j < 4; ++j) {
            ah[j] = prmt(cur[j].x, cur[j].y, 0x5410);
            al[j] = prmt(cur[j].x, cur[j].y, 0x7632);
        }
        if (kt + 4 < NKT) ldA(ab[kt & 3], kt + 4, src1, st1, src2, len1, r0, kq);

        uint2 bh[2], bl[2];
#pragma unroll
        for (int ntl = 0; ntl < 2; ++ntl) {
            int nt = ng * 2 + ntl;
            const uint32_t* wp = sW + (size_t)((nt * NKT + kt) * 2) * 64 + lane * 2;
            bh[ntl] = *(const uint2*)wp;
            bl[ntl] = *(const uint2*)(wp + 64);
        }
        // pass 1: hi·hi   pass 2: lo·hi   pass 3: hi·lo
#pragma unroll
        for (int ntl = 0; ntl < 2; ++ntl) mma16816(acc[ntl], ah, bh[ntl]);
#pragma unroll
        for (int ntl = 0; ntl < 2; ++ntl) mma16816(acc[ntl], al, bh[ntl]);
#pragma unroll
        for (int ntl = 0; ntl < 2; ++ntl) mma16816(acc[ntl], ah, bl[ntl]);
    }

    // epilogue: even lanes own cells; get (g,o) from odd neighbor via shfl.xor(1)
    const int q = lane & 3;
#pragma unroll
    for (int ntl = 0; ntl < 2; ++ntl) {
        int nt = ng * 2 + ntl;
        float* A = acc[ntl];
        float e0 = __shfl_xor_sync(0xffffffffu, A[0], 1);
        float e1 = __shfl_xor_sync(0xffffffffu, A[1], 1);
        float e2 = __shfl_xor_sync(0xffffffffu, A[2], 1);
        float e3 = __shfl_xor_sync(0xffffffffu, A[3], 1);
        if (!(lane & 1)) {
            int nb = nt * 8 + 2 * q;
            float bi = sbias[nb],     bfv = sbias[nb + 1];
            float bg = sbias[nb + 2], bo  = sbias[nb + 3];
            int jc = nt * 2 + (q >> 1);
            int row = mg * 16 + (lane >> 2);
#pragma unroll
            for (int rp = 0; rp < 2; ++rp) {
                float iv = A[rp * 2 + 0] + bi;
                float fv = A[rp * 2 + 1] + bfv;
                float gv = (rp ? e2 : e0) + bg;
                float ov = (rp ? e3 : e1) + bo;
                int ci = rp * 2 + ntl;
                float cn = sigm(fv) * cst[ci] + sigm(iv) * tanhf(gv);
                cst[ci] = cn;
                bounce[(row + rp * 8) * 8 + jc] = pack_split(sigm(ov) * tanhf(cn));
            }
        }
    }
    __syncthreads();
    {   // coalesced h store: 512 threads, one uint2 each (128 rows x 8 u32)
        int m = tid >> 2, j0 = (tid & 3) << 1;
        uint2 v = *(const uint2*)(bounce + m * 8 + j0);
        *(uint2*)(hOut + (size_t)m * H_ + jcol0 + j0) = v;
    }
}

// ---------------- persistent main kernel -----------------------------------------
__global__ void __launch_bounds__(NTHR, 1) lstm_main() {
    extern __shared__ uint32_t smw[];          // weights + bounce
    __shared__ float s_bias[32];
    uint32_t* bounce = smw + 32768;            // after 128KB weight region

    const int cta = blockIdx.x, tid = threadIdx.x;
    const bool isL1 = (cta >= 64);
    const int lc = isL1 ? cta - 64 : cta;
    const int jcol0 = lc * 8;

    // load resident weight fragment slice (contiguous)
    {
        const uint4* src = isL1 ? g_Wf1 : g_Wf0;
        const int NKT = isL1 ? NKT1 : NKT0;
        const uint4* s = src + (size_t)lc * 4 * NKT * 2 * 16;
        uint4* d = (uint4*)smw;
        for (int i = tid; i < NKT * 128; i += NTHR) d[i] = s[i];
        const float* gb = isL1 ? g_b1 : g_b0;
        if (tid < 32) s_bias[tid] = gb[lc * 32 + tid];
    }
    // zero h buffers each launch (deterministic)
    for (int i = cta * NTHR + tid; i < 4 * BH; i += NCTA * NTHR)
        ((uint32_t*)g_hp)[i] = 0u;

    unsigned relBase = *(volatile unsigned*)&g_release;
    unsigned gen = 0;
    float cst[4];
#pragma unroll
    for (int i = 0; i < 4; ++i) cst[i] = 0.f;

    gridBarrier(relBase + ++gen);

    for (int phase = 0; phase <= T_; ++phase) {
        if (!isL1) {
            if (phase < T_) {
                int t = phase;
                const uint32_t* hprev = g_hp[0][(t & 1) ^ 1];
                uint32_t* hout = g_hp[0][t & 1];
                lstm_phase<NKT0>(smw, g_xp + (size_t)t * B_ * D_, D_,
                                 hprev, D_, hout, cst, s_bias, bounce, jcol0);
            }
        } else if (phase >= 1) {
            int t = phase - 1;
            const uint32_t* h0cur = g_hp[0][t & 1];
            const uint32_t* h1prev = g_hp[1][(t & 1) ^ 1];
            uint32_t* hout = g_hp[1][t & 1];
            lstm_phase<NKT1>(smw, h0cur, H_, h1prev, H_,
                             hout, cst, s_bias, bounce, jcol0);
        }
        gridBarrier(relBase + ++gen);
    }
}

// ---------------- FC head ----------------------------------------------------------
__global__ void fc_head(const float* __restrict__ fc1w, const float* __restrict__ fc1b,
                        const float* __restrict__ fc2w, const float* __restrict__ fc2b,
                        float* __restrict__ out) {
    __shared__ float hsh[H_];
    __shared__ float hid[32];
    int b = blockIdx.x, tid = threadIdx.x;
    const uint32_t* h = g_hp[1][1] + (size_t)b * H_;   // t=511 odd -> buf1
#pragma unroll
    for (int r = 0; r < 2; ++r) {
        uint32_t u = h[tid + r * 256];
        hsh[tid + r * 256] =
            __bfloat162float(__ushort_as_bfloat16((unsigned short)(u & 0xFFFFu))) +
            __bfloat162float(__ushort_as_bfloat16((unsigned short)(u >> 16)));
    }
    __syncthreads();
    int w = tid >> 5, lane = tid & 31;
    for (int j = w; j < 32; j += 8) {
        const float* wr = fc1w + (size_t)j * H_;
        float s = 0.f;
        for (int k = lane; k < H_; k += 32) s += hsh[k] * wr[k];
#pragma unroll
        for (int off = 16; off; off >>= 1) s += __shfl_xor_sync(0xffffffffu, s, off);
        if (lane == 0) hid[j] = fmaxf(s + fc1b[j], 0.f) * fc2w[j];
    }
    __syncthreads();
    if (tid < 32) {
        float v = hid[tid];
#pragma unroll
        for (int off = 16; off; off >>= 1) v += __shfl_xor_sync(0xffffffffu, v, off);
        if (tid == 0) out[b] = v + fc2b[0];
    }
}

// ---------------- launch -------------------------------------------------------------
extern "C" void kernel_launch(void* const* d_in, const int* in_sizes, int n_in,
                              void* d_out, int out_size) {
    const float* x     = (const float*)d_in[0];
    const float* projw = (const float*)d_in[1];
    const float* projb = (const float*)d_in[2];
    const float* wx0   = (const float*)d_in[3];
    const float* bx0   = (const float*)d_in[4];
    const float* wh0   = (const float*)d_in[5];
    const float* bh0   = (const float*)d_in[6];
    const float* wx1   = (const float*)d_in[7];
    const float* bx1   = (const float*)d_in[8];
    const float* wh1   = (const float*)d_in[9];
    const float* bh1   = (const float*)d_in[10];
    const float* fc1w  = (const float*)d_in[11];
    const float* fc1b  = (const float*)d_in[12];
    const float* fc2w  = (const float*)d_in[13];
    const float* fc2b  = (const float*)d_in[14];
    float* out = (float*)d_out;

    const int SMEM_BYTES = 131072 + 4096;   // 128KB weights (L1 case) + 4KB bounce
    cudaFuncSetAttribute(lstm_main, cudaFuncAttributeMaxDynamicSharedMemorySize,
                         SMEM_BYTES);

    prep_x<<<2048, 256>>>(x);
    prep_w0<<<G_, D_>>>(wx0, projw, projb, bx0, bh0);
    prep_rest<<<2048, 256>>>(wh0, wx1, wh1, bx1, bh1);
    lstm_main<<<NCTA, NTHR, SMEM_BYTES>>>();
    fc_head<<<B_, 256>>>(fc1w, fc1b, fc2w, fc2b, out);
}

// round 11
// speedup vs baseline: 1.8210x; 1.8210x over previous
#include <cuda_runtime.h>
#include <cuda_bf16.h>
#include <cstdint>

#define B_   128
#define T_   512
#define D_   256
#define H_   512
#define G_   2048
#define K0_  768
#define K1_  1024
#define NKT0 (K0_ / 16)      // 48 ktiles
#define NKT1 (K1_ / 16)      // 64 ktiles
#define NCTA 128
#define BH   (B_ * H_)

// ---------------- persistent device scratch -----------------------------------
// Weight fragments: [ntg(256)][ktp][s=hi/lo][lane(32)][8 bf16]  (ktile pairs)
__device__ uint4 g_Wf0[(size_t)256 * NKT0 * 2 * 16];   // 6 MB
__device__ uint4 g_Wf1[(size_t)256 * NKT1 * 2 * 16];   // 8 MB
__device__ float g_b0[G_];
__device__ float g_b1[G_];
// Activations in MMA A-fragment order: per ktile block = [mg(8)][half(2)][lane(32)] uint4
__device__ uint4 g_xf[(size_t)T_ * 16 * 512];          // 64 MB
__device__ uint4 g_h0f[2][32 * 512];                   // 256 KB per buf
__device__ uint4 g_h1f[2][32 * 512];
__device__ unsigned g_count;
__device__ unsigned g_release;

// ---------------- helpers -------------------------------------------------------
__device__ __forceinline__ float sigm(float v) { return 1.f / (1.f + __expf(-v)); }

__device__ __forceinline__ uint32_t pack_split(float v) {
    __nv_bfloat16 h = __float2bfloat16(v);
    __nv_bfloat16 l = __float2bfloat16(v - __bfloat162float(h));
    return (uint32_t)__bfloat16_as_ushort(h) |
           ((uint32_t)__bfloat16_as_ushort(l) << 16);
}

__device__ __forceinline__ uint32_t prmt(uint32_t a, uint32_t b, uint32_t c) {
    uint32_t r;
    asm("prmt.b32 %0, %1, %2, %3;" : "=r"(r) : "r"(a), "r"(b), "r"(c));
    return r;
}

__device__ __forceinline__ void mma16816(float* d, const uint32_t* a, uint2 b) {
    asm volatile(
        "mma.sync.aligned.m16n8k16.row.col.f32.bf16.bf16.f32 "
        "{%0,%1,%2,%3}, {%4,%5,%6,%7}, {%8,%9}, {%0,%1,%2,%3};"
        : "+f"(d[0]), "+f"(d[1]), "+f"(d[2]), "+f"(d[3])
        : "r"(a[0]), "r"(a[1]), "r"(a[2]), "r"(a[3]), "r"(b.x), "r"(b.y));
}

__device__ __forceinline__ void gridBarrier(unsigned target) {
    __syncthreads();
    if (threadIdx.x == 0) {
        __threadfence();
        unsigned t = atomicAdd(&g_count, 1u);
        if (t == (unsigned)(NCTA - 1)) {
            g_count = 0;
            __threadfence();
            atomicAdd(&g_release, 1u);
        } else {
            while ((int)(*(volatile unsigned*)&g_release - target) < 0) {}
        }
        __threadfence();
    }
    __syncthreads();
}

// bf16-split store of W[np][k] into ktile-pair fragment layout (hi plane s=0, lo s=1)
__device__ __forceinline__ void wf_store(__nv_bfloat16* base, int NKTP,
                                         int np, int k, float v) {
    __nv_bfloat16 h = __float2bfloat16(v);
    __nv_bfloat16 l = __float2bfloat16(v - __bfloat162float(h));
    int ntg = np >> 3;
    int ln = ((np & 7) << 2) | ((k >> 1) & 3);   // B-frag: n = lane>>2, q = lane&3
    int kt = k >> 4, ktp = kt >> 1, kh = kt & 1;
    int b = (k >> 3) & 1, e = k & 1;
    size_t o = ((((size_t)ntg * NKTP + ktp) * 2) * 32 + ln) * 8 + kh * 4 + b * 2 + e;
    base[o] = h;
    base[o + 256] = l;   // s=1 plane is +32*8 bf16
}

// ---------------- prep kernels ---------------------------------------------------
// x -> fragment layout; one block per (t, mg), smem tile transpose.
__global__ void prep_x(const float* __restrict__ x) {
    __shared__ float sx[16 * 256];
    int blk = blockIdx.x;           // t*8 + mg
    int t = blk >> 3, mg = blk & 7;
    int tid = threadIdx.x;
    for (int i = tid; i < 16 * 256; i += 256) {
        int r = i >> 8, d = i & 255;
        sx[i] = x[(size_t)(mg * 16 + r) * T_ * D_ + (size_t)t * D_ + d];
    }
    __syncthreads();
    uint32_t* out = (uint32_t*)g_xf;
    for (int j = tid; j < 4096; j += 256) {
        int kt = j >> 8, rem = j & 255;
        int half = rem >> 7, r127 = rem & 127;
        int lane = r127 >> 2, e4 = r127 & 3;
        int r = (lane >> 2) + ((e4 >> 1) << 3);
        int d = kt * 16 + half * 8 + ((lane & 3) << 1) + (e4 & 1);
        out[((((size_t)t * 16 + kt) * 8 + mg) * 2 + half) * 128 + r127] =
            pack_split(sx[r * 256 + d]);
    }
}

// W0[np][k<256] = folded proj; b0
__global__ void prep_w0(const float* __restrict__ wx0, const float* __restrict__ projw,
                        const float* __restrict__ projb, const float* __restrict__ bx0,
                        const float* __restrict__ bh0) {
    int np = blockIdx.x;
    int jcol = np >> 2, q = np & 3;
    int n = q * H_ + jcol;
    int d = threadIdx.x;
    const float* wrow = wx0 + (size_t)n * D_;
    float acc = 0.f;
    for (int j = 0; j < D_; ++j) acc += wrow[j] * projw[(size_t)j * D_ + d];
    wf_store((__nv_bfloat16*)g_Wf0, NKT0 / 2, np, d, acc);
    if (d == 0) {
        float bb = bx0[n] + bh0[n];
        for (int j = 0; j < D_; ++j) bb += wrow[j] * projb[j];
        g_b0[np] = bb;
    }
}

// W0[np][k>=256] = wh0 ; W1 = [wx1|wh1] ; b1
__global__ void prep_rest(const float* __restrict__ wh0, const float* __restrict__ wx1,
                          const float* __restrict__ wh1, const float* __restrict__ bx1,
                          const float* __restrict__ bh1) {
    const int total = G_ * H_ + G_ * K1_ + G_;
    for (int i = blockIdx.x * blockDim.x + threadIdx.x; i < total;
         i += gridDim.x * blockDim.x) {
        if (i < G_ * H_) {
            int np = i / H_, k = i % H_;
            int n = (np & 3) * H_ + (np >> 2);
            wf_store((__nv_bfloat16*)g_Wf0, NKT0 / 2, np, D_ + k,
                     wh0[(size_t)n * H_ + k]);
        } else if (i < G_ * H_ + G_ * K1_) {
            int r = i - G_ * H_;
            int np = r / K1_, k = r % K1_;
            int n = (np & 3) * H_ + (np >> 2);
            float v = (k < H_) ? wx1[(size_t)n * H_ + k]
                               : wh1[(size_t)n * H_ + (k - H_)];
            wf_store((__nv_bfloat16*)g_Wf1, NKT1 / 2, np, k, v);
        } else {
            int np = i - G_ * H_ - G_ * K1_;
            int n = (np & 3) * H_ + (np >> 2);
            g_b1[np] = bx1[n] + bh1[n];
        }
    }
}

// ---------------- one LSTM phase: fragment-layout mma + cell epilogue ------------
// 8 warps, each M=16 rows x N=32 gate-cols; A from global in fragment order.
template <int NKT>
__device__ void lstm_phase(const uint32_t* __restrict__ sW,
    const uint4* __restrict__ pA, const uint4* __restrict__ pB, int split,
    uint4* __restrict__ hOutF, float* cst,
    const float* __restrict__ sbias, uint32_t* __restrict__ bounce, int lc) {
    constexpr int NKTP = NKT / 2;
    const int tid = threadIdx.x;
    const int lane = tid & 31, w = tid >> 5;
    const int mgl = w * 64 + lane;

    float acc[4][4];
#pragma unroll
    for (int j = 0; j < 4; ++j)
#pragma unroll
        for (int k = 0; k < 4; ++k) acc[j][k] = 0.f;

    uint4 ab[4][2];
#pragma unroll
    for (int p = 0; p < 4; ++p) {
        const uint4* s = ((p < split) ? pA + (size_t)p * 512
                                      : pB + (size_t)(p - split) * 512) + mgl;
        ab[p][0] = s[0];
        ab[p][1] = s[32];
    }
    const uint4* sW4 = (const uint4*)sW;

#pragma unroll 2
    for (int ktp = 0; ktp < NKTP; ++ktp) {
        uint4 bh[4], bl[4];
#pragma unroll
        for (int nt = 0; nt < 4; ++nt) {
            const uint4* wp = sW4 + (size_t)((nt * NKTP + ktp) * 2) * 32 + lane;
            bh[nt] = wp[0];
            bl[nt] = wp[32];
        }
#pragma unroll
        for (int half = 0; half < 2; ++half) {
            int kt = ktp * 2 + half;
            uint32_t* cur = (uint32_t*)ab[kt & 3];
            uint32_t ah[4], al[4];
#pragma unroll
            for (int j = 0; j < 4; ++j) {
                ah[j] = prmt(cur[2 * j], cur[2 * j + 1], 0x5410);
                al[j] = prmt(cur[2 * j], cur[2 * j + 1], 0x7632);
            }
            if (kt + 4 < NKT) {
                int kn = kt + 4;
                const uint4* s = ((kn < split) ? pA + (size_t)kn * 512
                                               : pB + (size_t)(kn - split) * 512) + mgl;
                ab[kt & 3][0] = s[0];
                ab[kt & 3][1] = s[32];
            }
            // pass 1: hi·hi   pass 2: lo·hi   pass 3: hi·lo
#pragma unroll
            for (int nt = 0; nt < 4; ++nt) {
                uint2 b2 = half ? make_uint2(bh[nt].z, bh[nt].w)
                                : make_uint2(bh[nt].x, bh[nt].y);
                mma16816(acc[nt], ah, b2);
            }
#pragma unroll
            for (int nt = 0; nt < 4; ++nt) {
                uint2 b2 = half ? make_uint2(bh[nt].z, bh[nt].w)
                                : make_uint2(bh[nt].x, bh[nt].y);
                mma16816(acc[nt], al, b2);
            }
#pragma unroll
            for (int nt = 0; nt < 4; ++nt) {
                uint2 b2 = half ? make_uint2(bl[nt].z, bl[nt].w)
                                : make_uint2(bl[nt].x, bl[nt].y);
                mma16816(acc[nt], ah, b2);
            }
        }
    }

    // epilogue: even lanes own cells; get (g,o) from odd neighbor via shfl.xor(1)
    const int q = lane & 3;
#pragma unroll
    for (int nt = 0; nt < 4; ++nt) {
        float* A = acc[nt];
        float e0 = __shfl_xor_sync(0xffffffffu, A[0], 1);
        float e1 = __shfl_xor_sync(0xffffffffu, A[1], 1);
        float e2 = __shfl_xor_sync(0xffffffffu, A[2], 1);
        float e3 = __shfl_xor_sync(0xffffffffu, A[3], 1);
        if (!(lane & 1)) {
            int nb = nt * 8 + 2 * q;
            float bi = sbias[nb],     bfv = sbias[nb + 1];
            float bg = sbias[nb + 2], bo  = sbias[nb + 3];
            int jc = nt * 2 + (q >> 1);
            int row = w * 16 + (lane >> 2);
#pragma unroll
            for (int rp = 0; rp < 2; ++rp) {
                float iv = A[rp * 2 + 0] + bi;
                float fv = A[rp * 2 + 1] + bfv;
                float gv = (rp ? e2 : e0) + bg;
                float ov = (rp ? e3 : e1) + bo;
                int ci = rp * 4 + nt;
                float cn = sigm(fv) * cst[ci] + sigm(iv) * tanhf(gv);
                cst[ci] = cn;
                bounce[(row + rp * 8) * 8 + jc] = pack_split(sigm(ov) * tanhf(cn));
            }
        }
    }
    __syncthreads();
    {   // fragment-order h store: one uint4 per thread, fully coalesced
        int rlo = lane >> 2, q2 = lane & 3;
        int row = w * 16 + rlo;
        uint4 v;
        v.x = bounce[row * 8 + 2 * q2];
        v.y = bounce[row * 8 + 2 * q2 + 1];
        v.z = bounce[(row + 8) * 8 + 2 * q2];
        v.w = bounce[(row + 8) * 8 + 2 * q2 + 1];
        hOutF[(size_t)(lc >> 1) * 512 + w * 64 + (lc & 1) * 32 + lane] = v;
    }
}

// ---------------- persistent main kernel -----------------------------------------
__global__ void __launch_bounds__(256, 1) lstm_main() {
    extern __shared__ uint32_t smw[];          // weights + bounce
    __shared__ float s_bias[32];
    uint32_t* bounce = smw + 32768;            // after 128KB weight region

    const int cta = blockIdx.x, tid = threadIdx.x;
    const bool isL1 = (cta >= 64);
    const int lc = isL1 ? cta - 64 : cta;

    // load resident weight fragment slice (contiguous)
    {
        const uint4* src = isL1 ? g_Wf1 : g_Wf0;
        const int NKT = isL1 ? NKT1 : NKT0;
        const uint4* s = src + (size_t)lc * NKT * 128;
        uint4* d = (uint4*)smw;
        for (int i = tid; i < NKT * 128; i += 256) d[i] = s[i];
        const float* gb = isL1 ? g_b1 : g_b0;
        if (tid < 32) s_bias[tid] = gb[lc * 32 + tid];
    }
    // zero h fragment buffers each launch (deterministic)
    {
        uint32_t* hz0 = (uint32_t*)g_h0f;
        uint32_t* hz1 = (uint32_t*)g_h1f;
        for (int i = cta * 256 + tid; i < 2 * 32 * 512 * 4; i += NCTA * 256) {
            hz0[i] = 0u;
            hz1[i] = 0u;
        }
    }

    unsigned relBase = *(volatile unsigned*)&g_release;
    unsigned gen = 0;
    float cst[8];
#pragma unroll
    for (int i = 0; i < 8; ++i) cst[i] = 0.f;

    gridBarrier(relBase + ++gen);

    for (int phase = 0; phase <= T_; ++phase) {
        if (!isL1) {
            if (phase < T_) {
                int t = phase;
                lstm_phase<NKT0>(smw, g_xf + (size_t)t * 16 * 512,
                                 g_h0f[(t & 1) ^ 1], 16,
                                 g_h0f[t & 1], cst, s_bias, bounce, lc);
            }
        } else if (phase >= 1) {
            int t = phase - 1;
            lstm_phase<NKT1>(smw, g_h0f[t & 1],
                             g_h1f[(t & 1) ^ 1], 32,
                             g_h1f[t & 1], cst, s_bias, bounce, lc);
        }
        gridBarrier(relBase + ++gen);
    }
}

// ---------------- FC head ----------------------------------------------------------
__global__ void fc_head(const float* __restrict__ fc1w, const float* __restrict__ fc1b,
                        const float* __restrict__ fc2w, const float* __restrict__ fc2b,
                        float* __restrict__ out) {
    __shared__ float hsh[H_];
    __shared__ float hid[32];
    int b = blockIdx.x, tid = threadIdx.x;
    const uint32_t* hf = (const uint32_t*)g_h1f[1];   // t=511 odd -> buf1
#pragma unroll
    for (int rr = 0; rr < 2; ++rr) {
        int col = tid + rr * 256;
        int kt = col >> 4, c16 = col & 15;
        int half = c16 >> 3, q = (c16 >> 1) & 3, e = c16 & 1;
        int r = b & 15, mg = b >> 4;
        int lane2 = ((r & 7) << 2) | q;
        int e4 = (((r >> 3) & 1) << 1) | e;
        uint32_t u = hf[((((size_t)kt * 8 + mg) * 2 + half) * 32 + lane2) * 4 + e4];
        hsh[col] =
            __bfloat162float(__ushort_as_bfloat16((unsigned short)(u & 0xFFFFu))) +
            __bfloat162float(__ushort_as_bfloat16((unsigned short)(u >> 16)));
    }
    __syncthreads();
    int w = tid >> 5, lane = tid & 31;
    for (int j = w; j < 32; j += 8) {
        const float* wr = fc1w + (size_t)j * H_;
        float s = 0.f;
        for (int k = lane; k < H_; k += 32) s += hsh[k] * wr[k];
#pragma unroll
        for (int off = 16; off; off >>= 1) s += __shfl_xor_sync(0xffffffffu, s, off);
        if (lane == 0) hid[j] = fmaxf(s + fc1b[j], 0.f) * fc2w[j];
    }
    __syncthreads();
    if (tid < 32) {
        float v = hid[tid];
#pragma unroll
        for (int off = 16; off; off >>= 1) v += __shfl_xor_sync(0xffffffffu, v, off);
        if (tid == 0) out[b] = v + fc2b[0];
    }
}

// ---------------- launch -------------------------------------------------------------
extern "C" void kernel_launch(void* const* d_in, const int* in_sizes, int n_in,
                              void* d_out, int out_size) {
    const float* x     = (const float*)d_in[0];
    const float* projw = (const float*)d_in[1];
    const float* projb = (const float*)d_in[2];
    const float* wx0   = (const float*)d_in[3];
    const float* bx0   = (const float*)d_in[4];
    const float* wh0   = (const float*)d_in[5];
    const float* bh0   = (const float*)d_in[6];
    const float* wx1   = (const float*)d_in[7];
    const float* bx1   = (const float*)d_in[8];
    const float* wh1   = (const float*)d_in[9];
    const float* bh1   = (const float*)d_in[10];
    const float* fc1w  = (const float*)d_in[11];
    const float* fc1b  = (const float*)d_in[12];
    const float* fc2w  = (const float*)d_in[13];
    const float* fc2b  = (const float*)d_in[14];
    float* out = (float*)d_out;

    const int SMEM_BYTES = 131072 + 4096;   // 128KB weights (L1 case) + 4KB bounce
    cudaFuncSetAttribute(lstm_main, cudaFuncAttributeMaxDynamicSharedMemorySize,
                         SMEM_BYTES);

    prep_x<<<T_ * 8, 256>>>(x);
    prep_w0<<<G_, D_>>>(wx0, projw, projb, bx0, bh0);
    prep_rest<<<2048, 256>>>(wh0, wx1, wh1, bx1, bh1);
    lstm_main<<<NCTA, 256, SMEM_BYTES>>>();
    fc_head<<<B_, 256>>>(fc1w, fc1b, fc2w, fc2b, out);
}